// round 17
// baseline (speedup 1.0000x reference)
#include <cuda_runtime.h>
#include <cuda_fp16.h>
#include <cstdint>

// ---------------- problem constants ----------------
#define N_TOTAL   4096
#define N_IN      1024
#define N_HID     2944
#define N_OUT     128
#define N_MROWS   3072          // matrix rows: nodes 1024..4095
#define BATCH     32
#define T_ITERS   100
#define DT_C      0.05f

// ---------------- kernel config --------------------
#define MAIN_BLOCKS   148
#define MAIN_THREADS  1024
#define MAIN_WARPS    (MAIN_THREADS / 32)              // 32
#define NCLUST        37                               // row-ranges per group
#define CLW           64                               // warps per 2-CTA cluster

#define NGROUPS        2                               // batch groups of 16
#define GB             16                              // batches per group

#define MAX_NNZ   (2 * 1024 * 1024)                    // expected ~815k padded
#define SMEM_CAP  368                                  // pairs per warp in smem
#define SLAB_BYTES (N_TOTAL * GB * 2)                  // 128 KB fp16 state slab
#define PAIR_BYTES (MAIN_WARPS * SMEM_CAP * 8)         // 94.2 KB
#define SMEM_BYTES (SLAB_BYTES + PAIR_BYTES)           // 220 KB < 227 KB cap
#define NSLOTS    4                                    // max chunks spanning a row

// pair word0 layout: [31:20]=row (12b), [16:5]=col*32 byte offset (col<<5)
// pair word1: J value as DUPLICATED half2 (both halves = J)
#define OFF_MASK  0x0001FFE0u

// prep mega-kernel block ranges (blockDim = 32x8 = 256)
#define PREP_NOISE_BLKS  (T_ITERS * (N_TOTAL / 64))    // 6400
#define PREP_X_BLKS      (N_IN / 32)                   // 32
#define PREP_CNT_BLKS    (N_MROWS / 8)                 // 384
#define PREP_BLKS        (PREP_NOISE_BLKS + PREP_X_BLKS + PREP_CNT_BLKS)

#define CLUSTER_ARRIVE() asm volatile("barrier.cluster.arrive.aligned;" ::: "memory")
#define CLUSTER_WAIT()   asm volatile("barrier.cluster.wait.aligned;" ::: "memory")

// acquire-poll until flag >= target (all lanes poll; same line -> broadcast)
__device__ __forceinline__ void poll_flag(const unsigned* addr, unsigned target) {
    unsigned v;
    do {
        asm volatile("ld.acquire.gpu.global.u32 %0, [%1];"
                     : "=r"(v) : "l"(addr) : "memory");
    } while ((int)(v - target) < 0);
}

// ---------------- device scratch (no allocs allowed) ----------------
__device__ __align__(16) uint2 g_pairs[MAX_NNZ];   // {row<<20|col<<5, half2 J}
__device__ int  g_row_start[N_MROWS + 1];          // padded-even prefix
__device__ int  g_row_cnt[N_MROWS];                // padded (even) counts
__device__ int  g_row_w0[N_MROWS];                 // first cluster-warp covering row
__device__ int  g_row_nslots[N_MROWS];             // #chunks spanning row (0..4)
__device__ int  g_clu_row[NCLUST + 1];             // row-range boundaries
__device__ int  g_clu_base[NCLUST + 1];            // pair-index boundaries
__device__ int  g_clu_W[NCLUST];                   // per-cluster chunk size (even)

__device__ float g_part[NGROUPS * N_MROWS * NSLOTS * GB]; // [g][row][slot][16]
// fp16 mirrors, TRIPLE buffered; layout [buf][g][node][16]
__device__ __align__(16) __half g_sm[3][NGROUPS * N_TOTAL * GB];
__device__ __align__(16) __half g_noiseT[(size_t)T_ITERS * N_TOTAL * BATCH]; // [t][node][b]
__device__ float g_xT[N_IN * BATCH];               // [node][b]
__device__ float g_inv_tau[N_TOTAL];

// dataflow flags: g_ctaflag[cta] = F0 + t + 1 after that CTA's phase2(t).
// Never reset; g_epoch grows by T_ITERS per invocation (bumped in fill_kernel)
// so flag targets increase monotonically across graph replays.
__device__ unsigned g_ctaflag[MAIN_BLOCKS];
__device__ unsigned g_epoch;

// ---------------- activation + state update (shared helper) ----------------
__device__ __forceinline__ float soen_update(float phi, float sold,
                                             float gam, float itau) {
    phi = fminf(fmaxf(phi, -0.5f), 0.5f);
    const float phip = (phi >= 0.5f) ? -0.5f : phi;   // periodic wrap
    const float gact = tanhf(phip) * (1.0f - sold);
    float snew = sold + DT_C * (gam * gact - sold * itau);
    return fminf(fmaxf(snew, -1.0f), 1.0f);
}

// ---------------- L0: mega-prep (transposes + counts + inv_tau) ----------------
__global__ void prep_kernel(const float* __restrict__ mask,
                            const float* __restrict__ tau,
                            const float* __restrict__ noise,
                            const float* __restrict__ x) {
    const unsigned blk = blockIdx.x;
    const int tx = threadIdx.x, ty = threadIdx.y;

    if (blk < PREP_NOISE_BLKS) {                   // noise transpose -> fp16
        __shared__ float tile[32][65];             // [b][node], 64 nodes
        const int t  = blk >> 6;                   // /64
        const int i0 = (blk & 63) * 64;
        for (int bb = ty; bb < 32; bb += 8) {
            const float2 v = *reinterpret_cast<const float2*>(
                noise + ((size_t)t * BATCH + bb) * N_TOTAL + i0 + 2 * tx);
            tile[bb][2 * tx]     = v.x;
            tile[bb][2 * tx + 1] = v.y;
        }
        __syncthreads();
        __half2* outp = reinterpret_cast<__half2*>(g_noiseT);
        const int l = tx & 15;
        for (int ii = ty * 2 + (tx >> 4); ii < 64; ii += 16) {
            const __half2 h = __floats2half2_rn(tile[2 * l][ii],
                                                tile[2 * l + 1][ii]);
            outp[((size_t)t * N_TOTAL + i0 + ii) * 16 + l] = h;
        }
        return;
    }
    if (blk < PREP_NOISE_BLKS + PREP_X_BLKS) {
        __shared__ float tile[32][33];
        const int xb = blk - PREP_NOISE_BLKS;
        const int i0 = xb * 32;
        for (int bb = ty; bb < 32; bb += 8)
            tile[bb][tx] = x[(size_t)bb * N_IN + i0 + tx];
        __syncthreads();
        for (int ii = ty; ii < 32; ii += 8)
            g_xT[(i0 + ii) * BATCH + tx] = tile[tx][ii];
        const int gt = xb * 256 + ty * 32 + tx;
        if (gt < N_TOTAL) g_inv_tau[gt] = 1.0f / tau[gt];
        return;
    }
    // row counts: warp per matrix row
    const int warp = (blk - PREP_NOISE_BLKS - PREP_X_BLKS) * 8 + ty;
    if (warp >= N_MROWS) return;
    const float* __restrict__ mrow = mask + (size_t)(N_IN + warp) * N_TOTAL;
    int cnt = 0;
    for (int j = tx; j < N_TOTAL; j += 32) {
        unsigned b = __ballot_sync(0xffffffffu, mrow[j] != 0.0f);
        cnt += __popc(b);
    }
    if (tx == 0) g_row_cnt[warp] = (cnt + 1) & ~1;   // pad to even
}

// ---------------- L1: prefix over padded counts + cluster row ranges ----------
__global__ void scan_kernel() {
    __shared__ int sh[32];
    const int t = threadIdx.x;      // 1024 threads
    int off = 0;
    for (int seg = 0; seg < 3; ++seg) {
        int v = g_row_cnt[seg * 1024 + t];
        int xv = v;
        #pragma unroll
        for (int d = 1; d < 32; d <<= 1) {
            int y = __shfl_up_sync(0xffffffffu, xv, d);
            if ((t & 31) >= d) xv += y;
        }
        if ((t & 31) == 31) sh[t >> 5] = xv;
        __syncthreads();
        if (t < 32) {
            int x2 = sh[t];
            #pragma unroll
            for (int d = 1; d < 32; d <<= 1) {
                int y = __shfl_up_sync(0xffffffffu, x2, d);
                if (t >= d) x2 += y;
            }
            sh[t] = x2;
        }
        __syncthreads();
        const int incl = xv + ((t >= 32) ? sh[(t >> 5) - 1] : 0);
        g_row_start[seg * 1024 + t] = off + incl - v;
        const int segtotal = sh[31];
        __syncthreads();
        off += segtotal;
    }
    const int total = off;                  // uniform across threads
    if (t == 0) g_row_start[N_MROWS] = total;
    __syncthreads();

    // cluster row boundaries: 37 weight-balanced contiguous ranges
    if (t <= NCLUST) {
        int r;
        if (t == 0) r = 0;
        else if (t == NCLUST) r = N_MROWS;
        else {
            const long long target = (long long)t * total / NCLUST;
            int lo = 0, hi = N_MROWS;       // smallest r with start[r] >= target
            while (lo < hi) {
                const int mid = (lo + hi) >> 1;
                if (g_row_start[mid] >= target) hi = mid; else lo = mid + 1;
            }
            r = lo;
        }
        g_clu_row[t]  = r;
        g_clu_base[t] = g_row_start[r];
    }
    __syncthreads();
    if (t < NCLUST) {
        const int diff = g_clu_base[t + 1] - g_clu_base[t];
        int w = (diff + CLW - 1) / CLW;
        w = (w + 1) & ~1;
        if (w < 2) w = 2;
        g_clu_W[t] = w;
    }
}

// ---------------- L2: fill flat pair array + per-row chunk metadata ----------------
__global__ void fill_kernel(const float* __restrict__ J,
                            const float* __restrict__ mask) {
    if (blockIdx.x == 0 && threadIdx.x == 0)
        g_epoch = g_epoch + T_ITERS;        // per-invocation epoch bump
    const int warp = (blockIdx.x * blockDim.x + threadIdx.x) >> 5;
    const int lane = threadIdx.x & 31;
    if (warp >= N_MROWS) return;
    const int row = N_IN + warp;
    const float* __restrict__ mrow = mask + (size_t)row * N_TOTAL;
    const float* __restrict__ jrow = J    + (size_t)row * N_TOTAL;
    const int base = g_row_start[warp];
    const unsigned rtag = (unsigned)warp << 20;

    int pos = base;
    for (int j = lane; j < N_TOTAL; j += 32) {
        const float mv = mrow[j];
        const bool  nz = (mv != 0.0f);
        unsigned b = __ballot_sync(0xffffffffu, nz);
        if (nz) {
            int idx = pos + __popc(b & ((1u << lane) - 1u));
            __half2 h2 = __float2half2_rn(jrow[j] * mv);   // duplicated fp16 J
            g_pairs[idx] = make_uint2(rtag | ((unsigned)j << 5),
                                      *reinterpret_cast<unsigned*>(&h2));
        }
        pos += __popc(b);
    }
    const int cnt = pos - base;
    if (lane == 0) {
        if (cnt & 1) g_pairs[base + cnt] = make_uint2(rtag, 0u);  // pad, val=0
        const int cnt_pad = (cnt + 1) & ~1;
        int k = 0;
        while (k < NCLUST - 1 && base >= g_clu_base[k + 1]) ++k;
        const int Wk = g_clu_W[k];
        int w0 = 0, nsl = 0;
        if (cnt_pad > 0) {
            w0  = (base - g_clu_base[k]) / Wk;
            nsl = (base + cnt_pad - 1 - g_clu_base[k]) / Wk - w0 + 1;
            if (nsl > NSLOTS) nsl = NSLOTS;
        }
        g_row_w0[warp]     = w0;
        g_row_nslots[warp] = nsl;
    }
}

// ---------------- L3: main persistent recurrence kernel ----------------
// BARRIER-FREE dataflow: no global barrier. Each CTA, after phase2(t), does
// __syncthreads (cumulative) + st.release flag = F0+t+1. The next iteration's
// slab fill polls, per chunk, only the two producer CTAs of the cluster that
// owns that mirror region (ld.acquire), then copies it — fast clusters copy
// early chunks while slow clusters finish. Mirror is TRIPLE buffered so
// phase2(t) [writes buf (t+1)%3] can never collide with any in-flight fill
// (fills read buf t%3; the flag RAW edges + per-CTA program order give
// phase2(t) happens-after every fill(t-2)). Partials are cross-CTA within a
// cluster only: cluster barrier (RAW) + flag edges (WAR) + __ldcg reads (no
// more IVALL to clean L1). fp32 state is register-resident (R16).
__global__ void __launch_bounds__(MAIN_THREADS, 1)
soen_main_kernel(const float* __restrict__ gamma,
                 const float* __restrict__ flux,
                 float* __restrict__ out) {
    extern __shared__ char smem_raw[];
    char*  slab     = smem_raw;                        // 128 KB fp16 state
    uint2* sh_pairs = (uint2*)(smem_raw + SLAB_BYTES); // pair chunks

    const int lane = threadIdx.x & 31;
    const int wcta = threadIdx.x >> 5;
    const int cid  = blockIdx.x >> 1;                  // cluster 0..73
    const int grp  = cid & 1;                          // batch group
    const int kcl  = cid >> 1;                         // row-range 0..36
    const int wic  = (blockIdx.x & 1) * 32 + wcta;     // warp-in-cluster 0..63
    const int p    = lane >> 1;                        // nnz position 0..15
    const int q    = lane & 1;                         // batch octet 0..1

    const unsigned F0 = g_epoch - T_ITERS;             // uniform this invocation

    const int Wk    = g_clu_W[kcl];
    const int cb    = g_clu_base[kcl];
    const int cend  = g_clu_base[kcl + 1];
    const int cbase = cb + wic * Wk;
    int n = cend - cbase;
    if (n > Wk) n = Wk;
    if (n < 0) n = 0;

    // stage this warp's pair chunk into smem (once; static schedule)
    const uint2* __restrict__ pbase;
    if (Wk <= SMEM_CAP) {
        uint2* mych = sh_pairs + wcta * SMEM_CAP;
        for (int j = lane; j < n; j += 32) mych[j] = g_pairs[cbase + j];
        __syncwarp();
        pbase = mych;
    } else {
        pbase = g_pairs + cbase;       // fallback (not expected)
    }

    const int r_lo = g_clu_row[kcl];
    const int r_hi = g_clu_row[kcl + 1];
    const int gw   = kcl * CLW + wic;                  // group-warp id (input map)
    const int bb   = lane & 15;
    const int b    = grp * GB + bb;

    // ---- static row ownership + cached constants (phase2 map is static) ----
    const int  ri0   = r_lo + wic * 2 + (lane >> 4);
    const int  ri1   = ri0 + 2 * CLW;
    const int  ri2   = ri1 + 2 * CLW;                  // safety (never expected)
    const bool own0  = ri0 < r_hi;
    const bool own1  = ri1 < r_hi;
    const bool own2  = ri2 < r_hi;
    const int  node0 = N_IN + ri0;

    float flux0 = 0.f, gam0 = 0.f, itau0 = 0.f;
    int   nsl0  = 0;
    const float* pp0 = g_part;
    if (own0) {
        flux0 = flux[node0];
        gam0  = gamma[node0];
        itau0 = g_inv_tau[node0];
        nsl0  = g_row_nslots[ri0];
        pp0   = g_part + ((grp * N_MROWS + ri0) * NSLOTS) * GB + bb;
    }
    const bool ownIn = (gw < N_IN) && (lane < GB);
    float biasI = 0.f, gamI = 0.f, itauI = 0.f;
    if (ownIn) {
        biasI = flux[gw] + g_xT[gw * BATCH + b];
        gamI  = gamma[gw];
        itauI = g_inv_tau[gw];
    }

    float s_own0 = 0.f, s_own1 = 0.f, s_own2 = 0.f, s_in = 0.f; // register state

    for (int t = 0; t < T_ITERS; ++t) {
        __half* dstm = g_sm[(t + 1) % 3] + grp * (N_TOTAL * GB);
        const __half* __restrict__ nzT = g_noiseT + (size_t)t * (N_TOTAL * BATCH);

        if (t > 0) {
            // ---- slab fill with per-chunk producer polling (dataflow) ----
            const __half* srcg = g_sm[t % 3] + grp * (N_TOTAL * GB);
            for (int ck = wcta; ck < NCLUST; ck += MAIN_WARPS) {
                const int cta0 = ((ck << 1) + grp) << 1;   // producer CTA pair
                poll_flag(&g_ctaflag[cta0],     F0 + t);
                poll_flag(&g_ctaflag[cta0 + 1], F0 + t);
                // hidden rows of range ck
                const int n0 = N_IN + g_clu_row[ck];
                const int n1 = N_IN + g_clu_row[ck + 1];
                const uint4* ms = reinterpret_cast<const uint4*>(srcg + n0 * GB);
                uint4*       md = reinterpret_cast<uint4*>(slab + n0 * GB * 2);
                const int cnt4 = (n1 - n0) * 2;            // uint4 per chunk
                for (int i = lane; i < cnt4; i += 32) md[i] = __ldcg(ms + i);
                if (ck < N_IN / 64) {                      // input nodes [64ck,+64)
                    const uint4* msI =
                        reinterpret_cast<const uint4*>(srcg + 64 * ck * GB);
                    uint4* mdI = reinterpret_cast<uint4*>(slab + 64 * ck * GB * 2);
                    for (int i = lane; i < 128; i += 32) mdI[i] = __ldcg(msI + i);
                }
            }
            __syncthreads();

            // ---- phase 1: balanced SpMM partials (HFMA2 on SMEM gathers) ----
            int pos = 0;
            while (pos < n) {
                const unsigned h0 = pbase[pos].x;
                const int row = (int)(h0 >> 20);
                int run_end = g_row_start[row + 1] - cbase;
                if (run_end > n) run_end = n;
                const int slot = wic - g_row_w0[row];

                __half2 c0 = __float2half2_rn(0.0f);
                __half2 c1 = c0, c2 = c0, c3 = c0;
                for (int kk = pos; kk < run_end; kk += 16) {
                    const int idx = kk + p;
                    if (idx < run_end) {
                        const uint2 pr = pbase[idx];
                        const uint4 hv = *reinterpret_cast<const uint4*>(
                            slab + (pr.x & OFF_MASK) + q * 16);
                        const __half2 jv = *reinterpret_cast<const __half2*>(&pr.y);
                        c0 = __hfma2(jv, *reinterpret_cast<const __half2*>(&hv.x), c0);
                        c1 = __hfma2(jv, *reinterpret_cast<const __half2*>(&hv.y), c1);
                        c2 = __hfma2(jv, *reinterpret_cast<const __half2*>(&hv.z), c2);
                        c3 = __hfma2(jv, *reinterpret_cast<const __half2*>(&hv.w), c3);
                    }
                }
                const float2 f0 = __half22float2(c0);
                const float2 f1 = __half22float2(c1);
                const float2 f2 = __half22float2(c2);
                const float2 f3 = __half22float2(c3);
                float a0 = f0.x, a1 = f0.y, a2 = f1.x, a3 = f1.y;
                float a4 = f2.x, a5 = f2.y, a6 = f3.x, a7 = f3.y;
                // reduce across nnz positions (lane bits 1..4) in fp32
                #pragma unroll
                for (int d = 2; d < 32; d <<= 1) {
                    a0 += __shfl_xor_sync(0xffffffffu, a0, d);
                    a1 += __shfl_xor_sync(0xffffffffu, a1, d);
                    a2 += __shfl_xor_sync(0xffffffffu, a2, d);
                    a3 += __shfl_xor_sync(0xffffffffu, a3, d);
                    a4 += __shfl_xor_sync(0xffffffffu, a4, d);
                    a5 += __shfl_xor_sync(0xffffffffu, a5, d);
                    a6 += __shfl_xor_sync(0xffffffffu, a6, d);
                    a7 += __shfl_xor_sync(0xffffffffu, a7, d);
                }
                if (p == 0 && slot >= 0 && slot < NSLOTS) {
                    float* pb2 = g_part +
                        (((grp * N_MROWS + row) * NSLOTS) + slot) * GB + q * 8;
                    *reinterpret_cast<float4*>(pb2)     = make_float4(a0, a1, a2, a3);
                    *reinterpret_cast<float4*>(pb2 + 4) = make_float4(a4, a5, a6, a7);
                }
                pos = run_end;
            }
        }

        // ---- input-node updates (register state; before cluster sync) ----
        if (ownIn) {
            const float phi = biasI + __half2float(nzT[gw * BATCH + b]);
            s_in = soen_update(phi, s_in, gamI, itauI);
            dstm[gw * GB + lane] = __float2half_rn(s_in);
        }

        // ---- prefetch phase2 inputs BEFORE the barrier (hide L2 latency) ----
        float nz0 = 0.f, nz1 = 0.f, nz2 = 0.f;
        float flux1 = 0.f, gam1 = 0.f, itau1 = 0.f;
        float flux2 = 0.f, gam2 = 0.f, itau2 = 0.f;
        int   nsl1 = 0, nsl2 = 0;
        if (own0) nz0 = __half2float(nzT[node0 * BATCH + b]);
        if (own1) {
            const int node1 = N_IN + ri1;
            nz1   = __half2float(nzT[node1 * BATCH + b]);
            flux1 = flux[node1];
            gam1  = gamma[node1];
            itau1 = g_inv_tau[node1];
            nsl1  = g_row_nslots[ri1];
        }
        if (own2) {
            const int node2 = N_IN + ri2;
            nz2   = __half2float(nzT[node2 * BATCH + b]);
            flux2 = flux[node2];
            gam2  = gamma[node2];
            itau2 = g_inv_tau[node2];
            nsl2  = g_row_nslots[ri2];
        }

        if (t > 0) {                  // partial visibility within cluster
            CLUSTER_ARRIVE();
            CLUSTER_WAIT();
        }

        // ---- phase 2: owned rows, register-resident state ----
        if (own0) {
            float phi = flux0 + nz0;
            if (t > 0) {
                #pragma unroll
                for (int sl = 0; sl < NSLOTS; ++sl)
                    if (sl < nsl0) phi += __ldcg(pp0 + sl * GB);
            }
            s_own0 = soen_update(phi, s_own0, gam0, itau0);
            dstm[node0 * GB + bb] = __float2half_rn(s_own0);
            if (t == T_ITERS - 1 && node0 >= N_IN + N_HID)
                out[(size_t)b * N_OUT + (node0 - (N_IN + N_HID))] = s_own0;
        }
        if (own1) {
            const int node1 = N_IN + ri1;
            float phi = flux1 + nz1;
            if (t > 0) {
                const float* pp1 =
                    g_part + ((grp * N_MROWS + ri1) * NSLOTS) * GB + bb;
                #pragma unroll
                for (int sl = 0; sl < NSLOTS; ++sl)
                    if (sl < nsl1) phi += __ldcg(pp1 + sl * GB);
            }
            s_own1 = soen_update(phi, s_own1, gam1, itau1);
            dstm[node1 * GB + bb] = __float2half_rn(s_own1);
            if (t == T_ITERS - 1 && node1 >= N_IN + N_HID)
                out[(size_t)b * N_OUT + (node1 - (N_IN + N_HID))] = s_own1;
        }
        if (own2) {
            const int node2 = N_IN + ri2;
            float phi = flux2 + nz2;
            if (t > 0) {
                const float* pp2 =
                    g_part + ((grp * N_MROWS + ri2) * NSLOTS) * GB + bb;
                #pragma unroll
                for (int sl = 0; sl < NSLOTS; ++sl)
                    if (sl < nsl2) phi += __ldcg(pp2 + sl * GB);
            }
            s_own2 = soen_update(phi, s_own2, gam2, itau2);
            dstm[node2 * GB + bb] = __float2half_rn(s_own2);
            if (t == T_ITERS - 1 && node2 >= N_IN + N_HID)
                out[(size_t)b * N_OUT + (node2 - (N_IN + N_HID))] = s_own2;
        }

        // ---- publish: all block writes -> release flag (replaces barrier) ----
        if (t != T_ITERS - 1) {
            __syncthreads();          // cumulative: all block STGs before release
            if (threadIdx.x == 0) {
                const unsigned v = F0 + t + 1;
                asm volatile("st.release.gpu.global.u32 [%0], %1;"
                             :: "l"(&g_ctaflag[blockIdx.x]), "r"(v) : "memory");
            }
        }
    }
}

// ---------------- launch: 4 launches, main at index 3 (ncu capture slot) ----
extern "C" void kernel_launch(void* const* d_in, const int* in_sizes, int n_in,
                              void* d_out, int out_size) {
    const float* x     = (const float*)d_in[0];   // [32, 1024]
    const float* J     = (const float*)d_in[1];   // [4096, 4096]
    const float* gamma = (const float*)d_in[2];   // [4096]
    const float* tau   = (const float*)d_in[3];   // [4096]
    const float* flux  = (const float*)d_in[4];   // [4096]
    const float* mask  = (const float*)d_in[5];   // [4096, 4096]
    const float* noise = (const float*)d_in[6];   // [100, 32, 4096]
    float* out = (float*)d_out;                   // [32, 128]
    (void)in_sizes; (void)n_in; (void)out_size;

    cudaFuncSetAttribute(soen_main_kernel,
                         cudaFuncAttributeMaxDynamicSharedMemorySize, SMEM_BYTES);

    prep_kernel<<<PREP_BLKS, dim3(32, 8)>>>(mask, tau, noise, x);      // idx 0
    scan_kernel<<<1, 1024>>>();                                        // idx 1
    fill_kernel<<<(N_MROWS * 32 + 255) / 256, 256>>>(J, mask);         // idx 2

    cudaLaunchConfig_t cfg = {};                                       // idx 3
    cfg.gridDim  = dim3(MAIN_BLOCKS, 1, 1);
    cfg.blockDim = dim3(MAIN_THREADS, 1, 1);
    cfg.dynamicSmemBytes = SMEM_BYTES;
    cudaLaunchAttribute attrs[1];
    attrs[0].id = cudaLaunchAttributeClusterDimension;
    attrs[0].val.clusterDim = {2, 1, 1};
    cfg.attrs = attrs;
    cfg.numAttrs = 1;
    cudaLaunchKernelEx(&cfg, soen_main_kernel, gamma, flux, out);
}